// round 1
// baseline (speedup 1.0000x reference)
#include <cuda_runtime.h>
#include <cuda_bf16.h>

// Problem constants
#define B_  8
#define T_  2048
#define D_  1024
#define H_  1024
#define R_  128
#define M_  (B_*T_)      // 16384 rows (b,t flattened)

// Scratch (device globals: allocation APIs are forbidden)
__device__ float d_tmp[M_ * 2 * R_];                 // [M, 256]: cols 0..127 = x@U1, 128..255 = x@U2
__device__ float d_bxby[(size_t)M_ * 2 * H_];        // [M, 2048]: cols 0..1023 = bx, 1024..2047 = by
__device__ float d_g[H_], d_phi[H_], d_gamma[H_];

// ---------------------------------------------------------------------------
// Per-channel decay parameters
// ---------------------------------------------------------------------------
__global__ void param_kernel(const float* __restrict__ nu_log,
                             const float* __restrict__ theta_log) {
    int h = blockIdx.x * blockDim.x + threadIdx.x;
    if (h < H_) {
        float r = expf(-expf(nu_log[h]));
        float th = expf(theta_log[h]);
        d_g[h]   = r * cosf(th);
        d_phi[h] = r * sinf(th);
        float om = 1.0f - r * r;
        d_gamma[h] = sqrtf(fmaxf(om, 0.0f));
    }
}

// ---------------------------------------------------------------------------
// fp32 SGEMM: C[64x64 tile] = A[M,K] * B[K,N]; optional gamma epilogue.
// 256 threads, 4x4 per thread, K-tile 16, float4 global I/O.
// All dims here are multiples of the tile sizes (M=16384, N in {128,1024},
// K in {1024,128}) so no bounds checks.
// ---------------------------------------------------------------------------
template <bool EPI>
__global__ void sgemm64(const float* __restrict__ A, int lda,
                        const float* __restrict__ Bm, int ldb,
                        float* __restrict__ C, int ldc, int K,
                        const float* __restrict__ gamma) {
    __shared__ float As[16][65];   // [k][m], padded
    __shared__ float Bs[16][64];   // [k][n]

    const int tid = threadIdx.x;
    const int tx = tid & 15;       // n group
    const int ty = tid >> 4;       // m group
    const int m0 = blockIdx.y * 64;
    const int n0 = blockIdx.x * 64;

    // A-tile loader mapping: 64 rows x 16 k, one float4 along k per thread
    const int am = tid >> 2;            // 0..63
    const int ak = (tid & 3) * 4;       // 0,4,8,12
    // B-tile loader mapping: 16 k x 64 n, one float4 along n per thread
    const int bk = tid >> 4;            // 0..15
    const int bn = (tid & 15) * 4;      // 0..60

    float acc[4][4] = {};

    for (int k0 = 0; k0 < K; k0 += 16) {
        float4 av = *(const float4*)(A + (size_t)(m0 + am) * lda + k0 + ak);
        float4 bv = *(const float4*)(Bm + (size_t)(k0 + bk) * ldb + n0 + bn);
        As[ak + 0][am] = av.x;
        As[ak + 1][am] = av.y;
        As[ak + 2][am] = av.z;
        As[ak + 3][am] = av.w;
        *(float4*)&Bs[bk][bn] = bv;
        __syncthreads();

#pragma unroll
        for (int k = 0; k < 16; k++) {
            float a[4];
#pragma unroll
            for (int i = 0; i < 4; i++) a[i] = As[k][ty * 4 + i];
            float4 bf = *(float4*)&Bs[k][tx * 4];
            float b[4] = {bf.x, bf.y, bf.z, bf.w};
#pragma unroll
            for (int i = 0; i < 4; i++)
#pragma unroll
                for (int j = 0; j < 4; j++)
                    acc[i][j] = fmaf(a[i], b[j], acc[i][j]);
        }
        __syncthreads();
    }

    float4 gv;
    if (EPI) gv = *(const float4*)&gamma[n0 + tx * 4];
#pragma unroll
    for (int i = 0; i < 4; i++) {
        int m = m0 + ty * 4 + i;
        float4 v = make_float4(acc[i][0], acc[i][1], acc[i][2], acc[i][3]);
        if (EPI) { v.x *= gv.x; v.y *= gv.y; v.z *= gv.z; v.w *= gv.w; }
        *(float4*)&C[(size_t)m * ldc + n0 + tx * 4] = v;
    }
}

// ---------------------------------------------------------------------------
// Serial per-channel scan: c_t = lambda * c_{t-1} + b_t  (complex, per h).
// One thread per (b,h); coalesced across h. Writes y = concat(c1,c2) and
// final states at the tail of the output buffer.
// ---------------------------------------------------------------------------
__global__ void scan_kernel(const float* __restrict__ bxby,
                            const float* __restrict__ hc1,
                            const float* __restrict__ hc2,
                            float* __restrict__ out) {
    int idx = blockIdx.x * blockDim.x + threadIdx.x;   // 0..8191
    int b = idx >> 10;
    int h = idx & (H_ - 1);

    float gg = d_g[h];
    float pp = d_phi[h];
    float c1 = hc1[idx];
    float c2 = hc2[idx];

    const float* base  = bxby + (size_t)b * T_ * (2 * H_) + h;
    float*       ybase = out  + (size_t)b * T_ * (2 * H_) + h;

#pragma unroll 4
    for (int t = 0; t < T_; t++) {
        float bx = base[t * (2 * H_)];
        float by = base[t * (2 * H_) + H_];
        float n1 = fmaf(gg, c1, fmaf(-pp, c2, bx));
        float n2 = fmaf(pp, c1, fmaf(gg, c2, by));
        c1 = n1;
        c2 = n2;
        ybase[t * (2 * H_)]      = c1;
        ybase[t * (2 * H_) + H_] = c2;
    }

    // finals after y
    size_t y_elems = (size_t)B_ * T_ * (2 * H_);
    out[y_elems + idx]            = c1;   // c1[:, -1, :]
    out[y_elems + B_ * H_ + idx]  = c2;   // c2[:, -1, :]
}

// ---------------------------------------------------------------------------
// Launch
// ---------------------------------------------------------------------------
extern "C" void kernel_launch(void* const* d_in, const int* in_sizes, int n_in,
                              void* d_out, int out_size) {
    const float* x         = (const float*)d_in[0];   // (B,T,D)
    const float* nu_log    = (const float*)d_in[1];   // (H)
    const float* theta_log = (const float*)d_in[2];   // (H)
    const float* U1        = (const float*)d_in[3];   // (D,R)
    const float* U2        = (const float*)d_in[4];   // (D,R)
    const float* V1        = (const float*)d_in[5];   // (R,H)
    const float* V2        = (const float*)d_in[6];   // (R,H)
    const float* hc1       = (const float*)d_in[7];   // (B,H)
    const float* hc2       = (const float*)d_in[8];   // (B,H)
    float* out = (float*)d_out;

    float *tmp, *bxby, *gamma;
    cudaGetSymbolAddress((void**)&tmp,   d_tmp);
    cudaGetSymbolAddress((void**)&bxby,  d_bxby);
    cudaGetSymbolAddress((void**)&gamma, d_gamma);

    param_kernel<<<(H_ + 255) / 256, 256>>>(nu_log, theta_log);

    // Stage 1: tmp[:,0:128] = x @ U1 ; tmp[:,128:256] = x @ U2   (K = 1024)
    sgemm64<false><<<dim3(R_ / 64, M_ / 64), 256>>>(x, D_, U1, R_, tmp,      2 * R_, D_, nullptr);
    sgemm64<false><<<dim3(R_ / 64, M_ / 64), 256>>>(x, D_, U2, R_, tmp + R_, 2 * R_, D_, nullptr);

    // Stage 2: bx = (tmp1 @ V1) * gamma ; by = (tmp2 @ V2) * gamma   (K = 128)
    sgemm64<true><<<dim3(H_ / 64, M_ / 64), 256>>>(tmp,      2 * R_, V1, H_, bxby,      2 * H_, R_, gamma);
    sgemm64<true><<<dim3(H_ / 64, M_ / 64), 256>>>(tmp + R_, 2 * R_, V2, H_, bxby + H_, 2 * H_, R_, gamma);

    // Stage 3: linear recurrence scan + output assembly
    scan_kernel<<<(B_ * H_) / 128, 128>>>(bxby, hc1, hc2, out);
}

// round 2
// speedup vs baseline: 1.2006x; 1.2006x over previous
#include <cuda_runtime.h>
#include <cuda_bf16.h>
#include <mma.h>

using namespace nvcuda;

// Problem constants
#define B_  8
#define T_  2048
#define D_  1024
#define H_  1024
#define R_  128
#define M_  (B_*T_)      // 16384 rows (b,t flattened)

// ---------------------------------------------------------------------------
// Scratch (device globals: allocation APIs are forbidden)
// ---------------------------------------------------------------------------
__device__ __nv_bfloat16 d_xhi[(size_t)M_ * D_];        // 32 MB
__device__ __nv_bfloat16 d_xlo[(size_t)M_ * D_];        // 32 MB
__device__ __nv_bfloat16 d_Uhi[D_ * 2 * R_];            // U1|U2 packed [D,256]
__device__ __nv_bfloat16 d_Ulo[D_ * 2 * R_];
__device__ __nv_bfloat16 d_V1hi[R_ * H_], d_V1lo[R_ * H_];
__device__ __nv_bfloat16 d_V2hi[R_ * H_], d_V2lo[R_ * H_];
__device__ __nv_bfloat16 d_thi[(size_t)M_ * 2 * R_];    // tmp hi [M,256]
__device__ __nv_bfloat16 d_tlo[(size_t)M_ * 2 * R_];    // tmp lo [M,256]
__device__ float d_bxby[(size_t)M_ * 2 * H_];           // 128 MB
__device__ float d_g[H_], d_phi[H_], d_gamma[H_];

// ---------------------------------------------------------------------------
// Per-channel decay parameters
// ---------------------------------------------------------------------------
__global__ void param_kernel(const float* __restrict__ nu_log,
                             const float* __restrict__ theta_log) {
    int h = blockIdx.x * blockDim.x + threadIdx.x;
    if (h < H_) {
        float r = expf(-expf(nu_log[h]));
        float th = expf(theta_log[h]);
        d_g[h]   = r * cosf(th);
        d_phi[h] = r * sinf(th);
        float om = 1.0f - r * r;
        d_gamma[h] = sqrtf(fmaxf(om, 0.0f));
    }
}

// ---------------------------------------------------------------------------
// fp32 -> bf16 hi/lo split converters
// ---------------------------------------------------------------------------
__device__ __forceinline__ void split_bf16(float v, __nv_bfloat16& hi, __nv_bfloat16& lo) {
    hi = __float2bfloat16(v);
    lo = __float2bfloat16(v - __bfloat162float(hi));
}

// x [M,D] -> xhi, xlo   (float4 grid-stride)
__global__ void conv_x_kernel(const float* __restrict__ x,
                              __nv_bfloat16* __restrict__ hi,
                              __nv_bfloat16* __restrict__ lo, int n4) {
    int i = blockIdx.x * blockDim.x + threadIdx.x;
    if (i >= n4) return;
    float4 v = ((const float4*)x)[i];
    __nv_bfloat16 h4[4], l4[4];
    split_bf16(v.x, h4[0], l4[0]);
    split_bf16(v.y, h4[1], l4[1]);
    split_bf16(v.z, h4[2], l4[2]);
    split_bf16(v.w, h4[3], l4[3]);
    ((uint2*)hi)[i] = *(uint2*)h4;
    ((uint2*)lo)[i] = *(uint2*)l4;
}

// U1,U2 [D,R] -> packed [D, 2R] hi/lo
__global__ void conv_U_kernel(const float* __restrict__ U1,
                              const float* __restrict__ U2) {
    int i = blockIdx.x * blockDim.x + threadIdx.x;   // 0..D*R-1
    if (i >= D_ * R_) return;
    int d = i / R_, r = i % R_;
    __nv_bfloat16 h, l;
    split_bf16(U1[i], h, l);
    d_Uhi[d * 2 * R_ + r] = h;  d_Ulo[d * 2 * R_ + r] = l;
    split_bf16(U2[i], h, l);
    d_Uhi[d * 2 * R_ + R_ + r] = h;  d_Ulo[d * 2 * R_ + R_ + r] = l;
}

// V1,V2 [R,H] -> hi/lo
__global__ void conv_V_kernel(const float* __restrict__ V1,
                              const float* __restrict__ V2) {
    int i = blockIdx.x * blockDim.x + threadIdx.x;   // 0..R*H-1
    if (i >= R_ * H_) return;
    __nv_bfloat16 h, l;
    split_bf16(V1[i], h, l);
    d_V1hi[i] = h;  d_V1lo[i] = l;
    split_bf16(V2[i], h, l);
    d_V2hi[i] = h;  d_V2lo[i] = l;
}

// ---------------------------------------------------------------------------
// Split-bf16 tensor-core GEMM: C = Ahi*Bhi + Ahi*Blo + Alo*Bhi
// Block tile 128x128, 512 threads (16 warps, each 32x32 via 2x2 wmma frags),
// K-tile 32. EPI=0: write C as bf16 hi/lo pair. EPI=1: C fp32 scaled by gamma.
// All dims are exact multiples of tiles; no bounds checks.
// ---------------------------------------------------------------------------
template <int EPI>
__global__ __launch_bounds__(512)
void mma_gemm(const __nv_bfloat16* __restrict__ Ahi,
              const __nv_bfloat16* __restrict__ Alo, int lda,
              const __nv_bfloat16* __restrict__ Bhi,
              const __nv_bfloat16* __restrict__ Blo, int ldb,
              int K,
              float* __restrict__ Cf,
              __nv_bfloat16* __restrict__ Chi,
              __nv_bfloat16* __restrict__ Clo, int ldc,
              const float* __restrict__ gamma) {
    constexpr int KT = 32;
    constexpr int ALD = KT + 8;      // 40 (mult of 8)
    constexpr int BLD = 128 + 8;     // 136 (mult of 8)

    __shared__ __align__(16) char smem_raw[128 * ALD * 2 + KT * BLD * 2];
    __nv_bfloat16 (*As)[ALD] = reinterpret_cast<__nv_bfloat16(*)[ALD]>(smem_raw);
    __nv_bfloat16 (*Bs)[BLD] = reinterpret_cast<__nv_bfloat16(*)[BLD]>(smem_raw + 128 * ALD * 2);
    float* epi = reinterpret_cast<float*>(smem_raw);   // 16 warps * 256 floats

    const int tid  = threadIdx.x;
    const int warp = tid >> 5;
    const int lane = tid & 31;
    const int wm = warp >> 2;        // 0..3
    const int wn = warp & 3;         // 0..3
    const int m0 = blockIdx.y * 128;
    const int n0 = blockIdx.x * 128;

    wmma::fragment<wmma::accumulator, 16, 16, 16, float> acc[2][2];
#pragma unroll
    for (int i = 0; i < 2; i++)
#pragma unroll
        for (int j = 0; j < 2; j++) wmma::fill_fragment(acc[i][j], 0.0f);

    // Loader mappings: 8 bf16 (16B) per thread
    const int ar = tid >> 2,  ac = (tid & 3) * 8;     // A: 128 x 32
    const int br = tid >> 4,  bc = (tid & 15) * 8;    // B: 32 x 128

    for (int pass = 0; pass < 3; pass++) {
        const __nv_bfloat16* Ap = (pass == 2) ? Alo : Ahi;
        const __nv_bfloat16* Bp = (pass == 1) ? Blo : Bhi;
        for (int k0 = 0; k0 < K; k0 += KT) {
            *(uint4*)&As[ar][ac] = *(const uint4*)(Ap + (size_t)(m0 + ar) * lda + k0 + ac);
            *(uint4*)&Bs[br][bc] = *(const uint4*)(Bp + (size_t)(k0 + br) * ldb + n0 + bc);
            __syncthreads();
#pragma unroll
            for (int ks = 0; ks < 2; ks++) {
                wmma::fragment<wmma::matrix_a, 16, 16, 16, __nv_bfloat16, wmma::row_major> af[2];
                wmma::fragment<wmma::matrix_b, 16, 16, 16, __nv_bfloat16, wmma::row_major> bf[2];
#pragma unroll
                for (int i = 0; i < 2; i++)
                    wmma::load_matrix_sync(af[i], &As[wm * 32 + i * 16][ks * 16], ALD);
#pragma unroll
                for (int j = 0; j < 2; j++)
                    wmma::load_matrix_sync(bf[j], &Bs[ks * 16][wn * 32 + j * 16], BLD);
#pragma unroll
                for (int i = 0; i < 2; i++)
#pragma unroll
                    for (int j = 0; j < 2; j++)
                        wmma::mma_sync(acc[i][j], af[i], bf[j], acc[i][j]);
            }
            __syncthreads();
        }
    }

    // Epilogue: stage each 16x16 frag through warp-private smem
    float* wbuf = epi + warp * 256;
    const int lr = lane >> 1;
    const int lc = (lane & 1) * 8;
#pragma unroll
    for (int i = 0; i < 2; i++) {
#pragma unroll
        for (int j = 0; j < 2; j++) {
            wmma::store_matrix_sync(wbuf, acc[i][j], 16, wmma::mem_row_major);
            __syncwarp();
            int m = m0 + wm * 32 + i * 16 + lr;
            int n = n0 + wn * 32 + j * 16 + lc;
            float v[8];
#pragma unroll
            for (int e = 0; e < 8; e++) v[e] = wbuf[lr * 16 + lc + e];
            if (EPI == 1) {
#pragma unroll
                for (int e = 0; e < 8; e++) v[e] *= gamma[n + e];
                *(float4*)&Cf[(size_t)m * ldc + n]     = make_float4(v[0], v[1], v[2], v[3]);
                *(float4*)&Cf[(size_t)m * ldc + n + 4] = make_float4(v[4], v[5], v[6], v[7]);
            } else {
                union { __nv_bfloat16 h[8]; uint4 u; } hv, lv;
#pragma unroll
                for (int e = 0; e < 8; e++) split_bf16(v[e], hv.h[e], lv.h[e]);
                *(uint4*)&Chi[(size_t)m * ldc + n] = hv.u;
                *(uint4*)&Clo[(size_t)m * ldc + n] = lv.u;
            }
            __syncwarp();
        }
    }
}

// ---------------------------------------------------------------------------
// Serial per-channel scan: c_t = lambda * c_{t-1} + b_t  (complex, per h).
// One thread per (b,h); coalesced across h.
// ---------------------------------------------------------------------------
__global__ void scan_kernel(const float* __restrict__ bxby,
                            const float* __restrict__ hc1,
                            const float* __restrict__ hc2,
                            float* __restrict__ out) {
    int idx = blockIdx.x * blockDim.x + threadIdx.x;   // 0..8191
    int b = idx >> 10;
    int h = idx & (H_ - 1);

    float gg = d_g[h];
    float pp = d_phi[h];
    float c1 = hc1[idx];
    float c2 = hc2[idx];

    const float* base  = bxby + (size_t)b * T_ * (2 * H_) + h;
    float*       ybase = out  + (size_t)b * T_ * (2 * H_) + h;

#pragma unroll 4
    for (int t = 0; t < T_; t++) {
        float bx = base[t * (2 * H_)];
        float by = base[t * (2 * H_) + H_];
        float n1 = fmaf(gg, c1, fmaf(-pp, c2, bx));
        float n2 = fmaf(pp, c1, fmaf(gg, c2, by));
        c1 = n1;
        c2 = n2;
        ybase[t * (2 * H_)]      = c1;
        ybase[t * (2 * H_) + H_] = c2;
    }

    size_t y_elems = (size_t)B_ * T_ * (2 * H_);
    out[y_elems + idx]           = c1;   // c1[:, -1, :]
    out[y_elems + B_ * H_ + idx] = c2;   // c2[:, -1, :]
}

// ---------------------------------------------------------------------------
// Launch
// ---------------------------------------------------------------------------
extern "C" void kernel_launch(void* const* d_in, const int* in_sizes, int n_in,
                              void* d_out, int out_size) {
    const float* x         = (const float*)d_in[0];   // (B,T,D)
    const float* nu_log    = (const float*)d_in[1];   // (H)
    const float* theta_log = (const float*)d_in[2];   // (H)
    const float* U1        = (const float*)d_in[3];   // (D,R)
    const float* U2        = (const float*)d_in[4];   // (D,R)
    const float* V1        = (const float*)d_in[5];   // (R,H)
    const float* V2        = (const float*)d_in[6];   // (R,H)
    const float* hc1       = (const float*)d_in[7];   // (B,H)
    const float* hc2       = (const float*)d_in[8];   // (B,H)
    float* out = (float*)d_out;

    __nv_bfloat16 *xhi, *xlo, *Uhi, *Ulo, *V1hi, *V1lo, *V2hi, *V2lo, *thi, *tlo;
    float *bxby, *gamma;
    cudaGetSymbolAddress((void**)&xhi,  d_xhi);
    cudaGetSymbolAddress((void**)&xlo,  d_xlo);
    cudaGetSymbolAddress((void**)&Uhi,  d_Uhi);
    cudaGetSymbolAddress((void**)&Ulo,  d_Ulo);
    cudaGetSymbolAddress((void**)&V1hi, d_V1hi);
    cudaGetSymbolAddress((void**)&V1lo, d_V1lo);
    cudaGetSymbolAddress((void**)&V2hi, d_V2hi);
    cudaGetSymbolAddress((void**)&V2lo, d_V2lo);
    cudaGetSymbolAddress((void**)&thi,  d_thi);
    cudaGetSymbolAddress((void**)&tlo,  d_tlo);
    cudaGetSymbolAddress((void**)&bxby, d_bxby);
    cudaGetSymbolAddress((void**)&gamma, d_gamma);

    param_kernel<<<(H_ + 255) / 256, 256>>>(nu_log, theta_log);

    // Conversions
    int n4 = (M_ * D_) / 4;
    conv_x_kernel<<<(n4 + 255) / 256, 256>>>(x, xhi, xlo, n4);
    conv_U_kernel<<<(D_ * R_ + 255) / 256, 256>>>(U1, U2);
    conv_V_kernel<<<(R_ * H_ + 255) / 256, 256>>>(V1, V2);

    // Stage 1: tmp[M,256] = x @ [U1|U2]   (K = 1024), output split to hi/lo
    mma_gemm<0><<<dim3(2 * R_ / 128, M_ / 128), 512>>>(
        xhi, xlo, D_, Uhi, Ulo, 2 * R_, D_,
        nullptr, thi, tlo, 2 * R_, nullptr);

    // Stage 2: bx = (tmp1 @ V1) * gamma ; by = (tmp2 @ V2) * gamma   (K = 128)
    mma_gemm<1><<<dim3(H_ / 128, M_ / 128), 512>>>(
        thi, tlo, 2 * R_, V1hi, V1lo, H_, R_,
        bxby, nullptr, nullptr, 2 * H_, gamma);
    mma_gemm<1><<<dim3(H_ / 128, M_ / 128), 512>>>(
        thi + R_, tlo + R_, 2 * R_, V2hi, V2lo, H_, R_,
        bxby + H_, nullptr, nullptr, 2 * H_, gamma);

    // Stage 3: linear recurrence scan + output assembly
    scan_kernel<<<(B_ * H_) / 128, 128>>>(bxby, hc1, hc2, out);
}

// round 4
// speedup vs baseline: 1.6542x; 1.3779x over previous
#include <cuda_runtime.h>
#include <cuda_bf16.h>
#include <mma.h>

using namespace nvcuda;

// Problem constants
#define B_  8
#define T_  2048
#define D_  1024
#define H_  1024
#define R_  128
#define M_  (B_*T_)      // 16384 rows (b,t flattened)
#define C_  16           // scan chunks
#define L_  128          // chunk length (T_ / C_), = 2^7

// ---------------------------------------------------------------------------
// Scratch (device globals: allocation APIs are forbidden)
// ---------------------------------------------------------------------------
__device__ __nv_bfloat16 d_Uhi[D_ * 2 * R_];            // U1|U2 packed [D,256]
__device__ __nv_bfloat16 d_Ulo[D_ * 2 * R_];
__device__ __nv_bfloat16 d_Vhi[R_ * 2 * H_];            // V1|V2 packed [R,2048]
__device__ __nv_bfloat16 d_Vlo[R_ * 2 * H_];
__device__ __nv_bfloat16 d_thi[(size_t)M_ * 2 * R_];    // tmp hi [M,256]
__device__ __nv_bfloat16 d_tlo[(size_t)M_ * 2 * R_];    // tmp lo [M,256]
__device__ float d_bxby[(size_t)M_ * 2 * H_];           // 128 MB
__device__ float d_e1[B_ * C_ * H_], d_e2[B_ * C_ * H_];     // chunk-local ends
__device__ float d_i1[B_ * C_ * H_], d_i2[B_ * C_ * H_];     // chunk inits
__device__ float d_g[H_], d_phi[H_], d_gamma[H_];

// ---------------------------------------------------------------------------
// Per-channel decay parameters
// ---------------------------------------------------------------------------
__global__ void param_kernel(const float* __restrict__ nu_log,
                             const float* __restrict__ theta_log) {
    int h = blockIdx.x * blockDim.x + threadIdx.x;
    if (h < H_) {
        float r = expf(-expf(nu_log[h]));
        float th = expf(theta_log[h]);
        d_g[h]   = r * cosf(th);
        d_phi[h] = r * sinf(th);
        float om = 1.0f - r * r;
        d_gamma[h] = sqrtf(fmaxf(om, 0.0f));
    }
}

__device__ __forceinline__ void split_bf16(float v, __nv_bfloat16& hi, __nv_bfloat16& lo) {
    hi = __float2bfloat16(v);
    lo = __float2bfloat16(v - __bfloat162float(hi));
}

// U1,U2 [D,R] -> packed [D, 2R] hi/lo
__global__ void conv_U_kernel(const float* __restrict__ U1,
                              const float* __restrict__ U2) {
    int i = blockIdx.x * blockDim.x + threadIdx.x;
    if (i >= D_ * R_) return;
    int d = i / R_, r = i % R_;
    __nv_bfloat16 h, l;
    split_bf16(U1[i], h, l);
    d_Uhi[d * 2 * R_ + r] = h;  d_Ulo[d * 2 * R_ + r] = l;
    split_bf16(U2[i], h, l);
    d_Uhi[d * 2 * R_ + R_ + r] = h;  d_Ulo[d * 2 * R_ + R_ + r] = l;
}

// V1,V2 [R,H] -> packed [R, 2H] hi/lo
__global__ void conv_V_kernel(const float* __restrict__ V1,
                              const float* __restrict__ V2) {
    int i = blockIdx.x * blockDim.x + threadIdx.x;
    if (i >= R_ * H_) return;
    int r = i / H_, h = i % H_;
    __nv_bfloat16 hh, ll;
    split_bf16(V1[i], hh, ll);
    d_Vhi[r * 2 * H_ + h] = hh;  d_Vlo[r * 2 * H_ + h] = ll;
    split_bf16(V2[i], hh, ll);
    d_Vhi[r * 2 * H_ + H_ + h] = hh;  d_Vlo[r * 2 * H_ + H_ + h] = ll;
}

// ---------------------------------------------------------------------------
// Split-bf16 tensor-core GEMM, all 3 products fused per K-tile.
//   C = Ahi*Bhi + Ahi*Blo + Alo*Bhi
// Block tile 128x64, 256 threads (8 warps, each a 32x32 subtile), K-tile 32.
// ASRC=0: A is fp32, converted to hi/lo while staging to smem.
// ASRC=1: A is pre-split bf16 (Ahi/Alo).
// DUAL=1: blocks with n0 >= H_ read A offset by +R_ columns (tmp2 @ V2 path).
// EPI=0: write C split to Chi/Clo.  EPI=1: write fp32 Cf scaled by gamma.
// ---------------------------------------------------------------------------
template <int ASRC, int EPI, int DUAL>
__global__ __launch_bounds__(256)
void mma_gemm(const float* __restrict__ Af,
              const __nv_bfloat16* __restrict__ Ahi,
              const __nv_bfloat16* __restrict__ Alo, int lda,
              const __nv_bfloat16* __restrict__ Bhi,
              const __nv_bfloat16* __restrict__ Blo, int ldb, int K,
              float* __restrict__ Cf,
              __nv_bfloat16* __restrict__ Chi,
              __nv_bfloat16* __restrict__ Clo, int ldc,
              const float* __restrict__ gamma) {
    constexpr int BM = 128, BN = 64, KT = 32;
    constexpr int ALD = KT + 8;   // 40
    constexpr int BLD = BN + 8;   // 72

    __shared__ __align__(16) __nv_bfloat16 AsH[BM][ALD];
    __shared__ __align__(16) __nv_bfloat16 AsL[BM][ALD];
    __shared__ __align__(16) __nv_bfloat16 BsH[KT][BLD];
    __shared__ __align__(16) __nv_bfloat16 BsL[KT][BLD];

    const int tid  = threadIdx.x;
    const int warp = tid >> 5;
    const int lane = tid & 31;
    const int wm = warp >> 1;          // 0..3
    const int wn = warp & 1;           // 0..1
    const int m0 = blockIdx.y * BM;
    const int n0 = blockIdx.x * BN;

    // DUAL: second output half reads the U2-projection columns of tmp
    const int aoff = (DUAL && n0 >= H_) ? R_ : 0;

    // Loader mappings
    const int ar = tid >> 1, ac = (tid & 1) * 16;   // A: 128 rows x 32 k, 16 els/thread
    const int br = tid >> 3, bc = (tid & 7) * 8;    // B: 32 k x 64 n, 8 els/thread

    wmma::fragment<wmma::accumulator, 16, 16, 16, float> acc[2][2];
#pragma unroll
    for (int i = 0; i < 2; i++)
#pragma unroll
        for (int j = 0; j < 2; j++) wmma::fill_fragment(acc[i][j], 0.0f);

    // Prefetch registers
    float4 pa[4];            // ASRC==0
    uint4  pah[2], pal[2];   // ASRC==1
    uint4  pbh, pbl;

    auto prefetch = [&](int k0) {
        if (ASRC == 0) {
            const float* ap = Af + (size_t)(m0 + ar) * lda + k0 + ac;
#pragma unroll
            for (int q = 0; q < 4; q++) pa[q] = *(const float4*)(ap + q * 4);
        } else {
            const __nv_bfloat16* aph = Ahi + (size_t)(m0 + ar) * lda + aoff + k0 + ac;
            const __nv_bfloat16* apl = Alo + (size_t)(m0 + ar) * lda + aoff + k0 + ac;
            pah[0] = *(const uint4*)aph;     pah[1] = *(const uint4*)(aph + 8);
            pal[0] = *(const uint4*)apl;     pal[1] = *(const uint4*)(apl + 8);
        }
        pbh = *(const uint4*)(Bhi + (size_t)(k0 + br) * ldb + n0 + bc);
        pbl = *(const uint4*)(Blo + (size_t)(k0 + br) * ldb + n0 + bc);
    };

    auto stage = [&]() {
        if (ASRC == 0) {
            union { __nv_bfloat16 h[8]; uint4 u; } hv, lv;
#pragma unroll
            for (int q = 0; q < 2; q++) {
                const float* f = (const float*)&pa[q * 2];
#pragma unroll
                for (int e = 0; e < 8; e++) split_bf16(f[e], hv.h[e], lv.h[e]);
                *(uint4*)&AsH[ar][ac + q * 8] = hv.u;
                *(uint4*)&AsL[ar][ac + q * 8] = lv.u;
            }
        } else {
            *(uint4*)&AsH[ar][ac]     = pah[0];
            *(uint4*)&AsH[ar][ac + 8] = pah[1];
            *(uint4*)&AsL[ar][ac]     = pal[0];
            *(uint4*)&AsL[ar][ac + 8] = pal[1];
        }
        *(uint4*)&BsH[br][bc] = pbh;
        *(uint4*)&BsL[br][bc] = pbl;
    };

    prefetch(0);
    for (int k0 = 0; k0 < K; k0 += KT) {
        stage();
        __syncthreads();
        if (k0 + KT < K) prefetch(k0 + KT);

#pragma unroll
        for (int ks = 0; ks < 2; ks++) {
            wmma::fragment<wmma::matrix_a, 16, 16, 16, __nv_bfloat16, wmma::row_major> af[2];
            wmma::fragment<wmma::matrix_b, 16, 16, 16, __nv_bfloat16, wmma::row_major> bf[2];
            // Ahi * Bhi
#pragma unroll
            for (int i = 0; i < 2; i++)
                wmma::load_matrix_sync(af[i], &AsH[wm * 32 + i * 16][ks * 16], ALD);
#pragma unroll
            for (int j = 0; j < 2; j++)
                wmma::load_matrix_sync(bf[j], &BsH[ks * 16][wn * 32 + j * 16], BLD);
#pragma unroll
            for (int i = 0; i < 2; i++)
#pragma unroll
                for (int j = 0; j < 2; j++) wmma::mma_sync(acc[i][j], af[i], bf[j], acc[i][j]);
            // Ahi * Blo
#pragma unroll
            for (int j = 0; j < 2; j++)
                wmma::load_matrix_sync(bf[j], &BsL[ks * 16][wn * 32 + j * 16], BLD);
#pragma unroll
            for (int i = 0; i < 2; i++)
#pragma unroll
                for (int j = 0; j < 2; j++) wmma::mma_sync(acc[i][j], af[i], bf[j], acc[i][j]);
            // Alo * Bhi
#pragma unroll
            for (int i = 0; i < 2; i++)
                wmma::load_matrix_sync(af[i], &AsL[wm * 32 + i * 16][ks * 16], ALD);
#pragma unroll
            for (int j = 0; j < 2; j++)
                wmma::load_matrix_sync(bf[j], &BsH[ks * 16][wn * 32 + j * 16], BLD);
#pragma unroll
            for (int i = 0; i < 2; i++)
#pragma unroll
                for (int j = 0; j < 2; j++) wmma::mma_sync(acc[i][j], af[i], bf[j], acc[i][j]);
        }
        __syncthreads();
    }

    // Epilogue: stage 16x16 frags through warp-private smem (reuse AsH)
    float* epi = (float*)&AsH[0][0];
    float* wbuf = epi + warp * 256;
    const int lr = lane >> 1;
    const int lc = (lane & 1) * 8;
#pragma unroll
    for (int i = 0; i < 2; i++) {
#pragma unroll
        for (int j = 0; j < 2; j++) {
            wmma::store_matrix_sync(wbuf, acc[i][j], 16, wmma::mem_row_major);
            __syncwarp();
            int m = m0 + wm * 32 + i * 16 + lr;
            int n = n0 + wn * 32 + j * 16 + lc;
            float v[8];
#pragma unroll
            for (int e = 0; e < 8; e++) v[e] = wbuf[lr * 16 + lc + e];
            if (EPI == 1) {
#pragma unroll
                for (int e = 0; e < 8; e++) v[e] *= gamma[(n & (H_ - 1)) + e];
                *(float4*)&Cf[(size_t)m * ldc + n]     = make_float4(v[0], v[1], v[2], v[3]);
                *(float4*)&Cf[(size_t)m * ldc + n + 4] = make_float4(v[4], v[5], v[6], v[7]);
            } else {
                union { __nv_bfloat16 h[8]; uint4 u; } hv, lv;
#pragma unroll
                for (int e = 0; e < 8; e++) split_bf16(v[e], hv.h[e], lv.h[e]);
                *(uint4*)&Chi[(size_t)m * ldc + n] = hv.u;
                *(uint4*)&Clo[(size_t)m * ldc + n] = lv.u;
            }
            __syncwarp();
        }
    }
}

// ---------------------------------------------------------------------------
// Chunk-parallel scan.  idx -> (b, chunk j, h);  h fastest for coalescing.
// ---------------------------------------------------------------------------
__global__ void scanA_kernel(const float* __restrict__ bxby,
                             float* __restrict__ e1, float* __restrict__ e2) {
    int idx = blockIdx.x * blockDim.x + threadIdx.x;    // B*C*H
    int h = idx & (H_ - 1);
    int j = (idx >> 10) & (C_ - 1);
    int b = idx >> 14;
    float gg = d_g[h], pp = d_phi[h];
    float c1 = 0.f, c2 = 0.f;
    const float* base = bxby + ((size_t)(b * T_ + j * L_)) * (2 * H_) + h;
#pragma unroll 4
    for (int t = 0; t < L_; t++) {
        float bx = base[t * (2 * H_)];
        float by = base[t * (2 * H_) + H_];
        float n1 = fmaf(gg, c1, fmaf(-pp, c2, bx));
        float n2 = fmaf(pp, c1, fmaf(gg, c2, by));
        c1 = n1; c2 = n2;
    }
    e1[idx] = c1; e2[idx] = c2;
}

__global__ void combine_kernel(const float* __restrict__ e1,
                               const float* __restrict__ e2,
                               const float* __restrict__ hc1,
                               const float* __restrict__ hc2,
                               float* __restrict__ i1, float* __restrict__ i2) {
    int idx = blockIdx.x * blockDim.x + threadIdx.x;    // B*H
    int h = idx & (H_ - 1);
    int b = idx >> 10;
    // lambda^L by 7 complex squarings (L = 128 = 2^7)
    float lr = d_g[h], li = d_phi[h];
#pragma unroll
    for (int s = 0; s < 7; s++) {
        float nr = lr * lr - li * li;
        float ni = 2.0f * lr * li;
        lr = nr; li = ni;
    }
    float c1 = hc1[idx], c2 = hc2[idx];
#pragma unroll
    for (int j = 0; j < C_; j++) {
        int eidx = (b * C_ + j) * H_ + h;
        i1[eidx] = c1; i2[eidx] = c2;
        float n1 = lr * c1 - li * c2 + e1[eidx];
        float n2 = li * c1 + lr * c2 + e2[eidx];
        c1 = n1; c2 = n2;
    }
}

__global__ void scanB_kernel(const float* __restrict__ bxby,
                             const float* __restrict__ i1,
                             const float* __restrict__ i2,
                             float* __restrict__ out) {
    int idx = blockIdx.x * blockDim.x + threadIdx.x;    // B*C*H
    int h = idx & (H_ - 1);
    int j = (idx >> 10) & (C_ - 1);
    int b = idx >> 14;
    float gg = d_g[h], pp = d_phi[h];
    float c1 = i1[idx], c2 = i2[idx];
    const float* base  = bxby + ((size_t)(b * T_ + j * L_)) * (2 * H_) + h;
    float*       ybase = out  + ((size_t)(b * T_ + j * L_)) * (2 * H_) + h;
#pragma unroll 4
    for (int t = 0; t < L_; t++) {
        float bx = base[t * (2 * H_)];
        float by = base[t * (2 * H_) + H_];
        float n1 = fmaf(gg, c1, fmaf(-pp, c2, bx));
        float n2 = fmaf(pp, c1, fmaf(gg, c2, by));
        c1 = n1; c2 = n2;
        ybase[t * (2 * H_)]      = c1;
        ybase[t * (2 * H_) + H_] = c2;
    }
    if (j == C_ - 1) {
        size_t y_elems = (size_t)B_ * T_ * (2 * H_);
        out[y_elems + b * H_ + h]            = c1;
        out[y_elems + B_ * H_ + b * H_ + h]  = c2;
    }
}

// ---------------------------------------------------------------------------
// Launch
// ---------------------------------------------------------------------------
extern "C" void kernel_launch(void* const* d_in, const int* in_sizes, int n_in,
                              void* d_out, int out_size) {
    const float* x         = (const float*)d_in[0];
    const float* nu_log    = (const float*)d_in[1];
    const float* theta_log = (const float*)d_in[2];
    const float* U1        = (const float*)d_in[3];
    const float* U2        = (const float*)d_in[4];
    const float* V1        = (const float*)d_in[5];
    const float* V2        = (const float*)d_in[6];
    const float* hc1       = (const float*)d_in[7];
    const float* hc2       = (const float*)d_in[8];
    float* out = (float*)d_out;

    __nv_bfloat16 *Uhi, *Ulo, *Vhi, *Vlo, *thi, *tlo;
    float *bxby, *gamma, *e1, *e2, *i1, *i2;
    cudaGetSymbolAddress((void**)&Uhi,  d_Uhi);
    cudaGetSymbolAddress((void**)&Ulo,  d_Ulo);
    cudaGetSymbolAddress((void**)&Vhi,  d_Vhi);
    cudaGetSymbolAddress((void**)&Vlo,  d_Vlo);
    cudaGetSymbolAddress((void**)&thi,  d_thi);
    cudaGetSymbolAddress((void**)&tlo,  d_tlo);
    cudaGetSymbolAddress((void**)&bxby, d_bxby);
    cudaGetSymbolAddress((void**)&gamma, d_gamma);
    cudaGetSymbolAddress((void**)&e1, d_e1);
    cudaGetSymbolAddress((void**)&e2, d_e2);
    cudaGetSymbolAddress((void**)&i1, d_i1);
    cudaGetSymbolAddress((void**)&i2, d_i2);

    param_kernel<<<(H_ + 255) / 256, 256>>>(nu_log, theta_log);
    conv_U_kernel<<<(D_ * R_ + 255) / 256, 256>>>(U1, U2);
    conv_V_kernel<<<(R_ * H_ + 255) / 256, 256>>>(V1, V2);

    // Stage 1: tmp[M,256] = x @ [U1|U2]  (K=1024); x converted in-kernel.
    mma_gemm<0, 0, 0><<<dim3(2 * R_ / 64, M_ / 128), 256>>>(
        x, nullptr, nullptr, D_, Uhi, Ulo, 2 * R_, D_,
        nullptr, thi, tlo, 2 * R_, nullptr);

    // Stage 2: bxby[:, 0:H]  = (tmp1 @ V1) * gamma
    //          bxby[:, H:2H] = (tmp2 @ V2) * gamma   (DUAL selects tmp half by n0)
    mma_gemm<1, 1, 1><<<dim3(2 * H_ / 64, M_ / 128), 256>>>(
        nullptr, thi, tlo, 2 * R_, Vhi, Vlo, 2 * H_, R_,
        bxby, nullptr, nullptr, 2 * H_, gamma);

    // Stage 3: chunk-parallel scan
    scanA_kernel<<<(B_ * C_ * H_) / 256, 256>>>(bxby, e1, e2);
    combine_kernel<<<(B_ * H_) / 256, 256>>>(e1, e2, hc1, hc2, i1, i2);
    scanB_kernel<<<(B_ * C_ * H_) / 256, 256>>>(bxby, i1, i2, out);
}

// round 6
// speedup vs baseline: 2.1994x; 1.3295x over previous
#include <cuda_runtime.h>
#include <cuda_bf16.h>
#include <cstdint>
#include <mma.h>

using namespace nvcuda;

// Problem constants
#define B_  8
#define T_  2048
#define D_  1024
#define H_  1024
#define R_  128
#define M_  (B_*T_)      // 16384 rows
#define C_  16           // scan chunks
#define L_  128          // chunk length (T_/C_) = 2^7

// ---------------------------------------------------------------------------
// Scratch (device globals: allocation APIs are forbidden)
// ---------------------------------------------------------------------------
__device__ float d_tmp[(size_t)M_ * 2 * R_];            // [M,256]: x@U1 | x@U2 (fp32)
__device__ float d_bxby[(size_t)M_ * 2 * H_];           // 128 MB
__device__ float d_e1[B_ * C_ * H_], d_e2[B_ * C_ * H_];
__device__ float d_i1[B_ * C_ * H_], d_i2[B_ * C_ * H_];
__device__ float d_g[H_], d_phi[H_], d_gamma[H_];

// ---------------------------------------------------------------------------
// Per-channel decay parameters
// ---------------------------------------------------------------------------
__global__ void param_kernel(const float* __restrict__ nu_log,
                             const float* __restrict__ theta_log) {
    int h = blockIdx.x * blockDim.x + threadIdx.x;
    if (h < H_) {
        float r = expf(-expf(nu_log[h]));
        float th = expf(theta_log[h]);
        d_g[h]   = r * cosf(th);
        d_phi[h] = r * sinf(th);
        float om = 1.0f - r * r;
        d_gamma[h] = sqrtf(fmaxf(om, 0.0f));
    }
}

// ---------------------------------------------------------------------------
// cp.async helpers
// ---------------------------------------------------------------------------
__device__ __forceinline__ void cp_async16(void* dst, const void* src) {
    unsigned s = (unsigned)__cvta_generic_to_shared(dst);
    asm volatile("cp.async.ca.shared.global [%0], [%1], 16;" :: "r"(s), "l"(src));
}
__device__ __forceinline__ void cp_commit() { asm volatile("cp.async.commit_group;"); }
template <int N>
__device__ __forceinline__ void cp_wait() { asm volatile("cp.async.wait_group %0;" :: "n"(N)); }

// ---------------------------------------------------------------------------
// tf32 tensor-core GEMM, double-buffered cp.async pipeline.
//   C[M, 2N'] where columns [0,nsplit) use B0 and [nsplit,..) use B1.
// DUALA=1: blocks with n0 >= nsplit read A shifted by +R_ cols (tmp2 path).
// EPI=1: multiply by gamma[n % H] on store.
// Tiles: BM=128, BN=64, KT=16; 256 threads, 8 warps (4x2) of 32x32.
// ---------------------------------------------------------------------------
template <int DUALA, int EPI>
__global__ __launch_bounds__(256, 2)
void tf32_gemm(const float* __restrict__ A, int lda,
               const float* __restrict__ B0, const float* __restrict__ B1,
               int ldb, int nsplit, int K,
               float* __restrict__ C, int ldc,
               const float* __restrict__ gamma) {
    constexpr int BM = 128, BN = 64, KT = 16;
    constexpr int ALD = KT + 4;   // 20 floats (80B row, 16B-aligned)
    constexpr int BLD = BN + 4;   // 68 floats (272B row, 16B-aligned)

    __shared__ __align__(16) float As[2][BM][ALD];
    __shared__ __align__(16) float Bs[2][KT][BLD];

    const int tid  = threadIdx.x;
    const int warp = tid >> 5;
    const int lane = tid & 31;
    const int wm = warp >> 1;        // 0..3
    const int wn = warp & 1;         // 0..1
    const int m0 = blockIdx.y * BM;
    const int n0 = blockIdx.x * BN;

    const float* Bp = (n0 >= nsplit) ? B1 : B0;
    const int bn0   = (n0 >= nsplit) ? n0 - nsplit : n0;
    const int aoff  = (DUALA && n0 >= nsplit) ? R_ : 0;

    // Loader mappings (16B chunks)
    const int a_row = tid >> 2,  a_col = (tid & 3) * 4;    // A: 128x16, 2 chunks/thread
    const int b_row = tid >> 4,  b_col = (tid & 15) * 4;   // B: 16x64, 1 chunk/thread

    auto load_stage = [&](int s, int k0) {
        const float* ap = A + (size_t)(m0 + a_row) * lda + aoff + k0 + a_col;
        cp_async16(&As[s][a_row][a_col],      ap);
        cp_async16(&As[s][a_row + 64][a_col], ap + (size_t)64 * lda);
        cp_async16(&Bs[s][b_row][b_col],
                   Bp + (size_t)(k0 + b_row) * ldb + bn0 + b_col);
        cp_commit();
    };

    wmma::fragment<wmma::accumulator, 16, 16, 8, float> acc[2][2];
#pragma unroll
    for (int i = 0; i < 2; i++)
#pragma unroll
        for (int j = 0; j < 2; j++) wmma::fill_fragment(acc[i][j], 0.0f);

    const int nK = K / KT;
    load_stage(0, 0);

    for (int kt = 0; kt < nK; kt++) {
        const int s = kt & 1;
        if (kt + 1 < nK) {
            load_stage(1 - s, (kt + 1) * KT);
            cp_wait<1>();
        } else {
            cp_wait<0>();
        }
        __syncthreads();

#pragma unroll
        for (int ks = 0; ks < 2; ks++) {
            wmma::fragment<wmma::matrix_a, 16, 16, 8, wmma::precision::tf32, wmma::row_major> af[2];
            wmma::fragment<wmma::matrix_b, 16, 16, 8, wmma::precision::tf32, wmma::row_major> bf[2];
#pragma unroll
            for (int i = 0; i < 2; i++) {
                wmma::load_matrix_sync(af[i], &As[s][wm * 32 + i * 16][ks * 8], ALD);
#pragma unroll
                for (int t = 0; t < af[i].num_elements; t++)
                    af[i].x[t] = wmma::__float_to_tf32(af[i].x[t]);
            }
#pragma unroll
            for (int j = 0; j < 2; j++) {
                wmma::load_matrix_sync(bf[j], &Bs[s][ks * 8][wn * 32 + j * 16], BLD);
#pragma unroll
                for (int t = 0; t < bf[j].num_elements; t++)
                    bf[j].x[t] = wmma::__float_to_tf32(bf[j].x[t]);
            }
#pragma unroll
            for (int i = 0; i < 2; i++)
#pragma unroll
                for (int j = 0; j < 2; j++)
                    wmma::mma_sync(acc[i][j], af[i], bf[j], acc[i][j]);
        }
        __syncthreads();
    }

    // Epilogue: stage 16x16 frags through warp-private smem (reuse As)
    float* wbuf = (float*)&As[0][0][0] + warp * 256;
    const int lr = lane >> 1;
    const int lc = (lane & 1) * 8;
#pragma unroll
    for (int i = 0; i < 2; i++) {
#pragma unroll
        for (int j = 0; j < 2; j++) {
            wmma::store_matrix_sync(wbuf, acc[i][j], 16, wmma::mem_row_major);
            __syncwarp();
            int m = m0 + wm * 32 + i * 16 + lr;
            int n = n0 + wn * 32 + j * 16 + lc;
            float v[8];
#pragma unroll
            for (int e = 0; e < 8; e++) v[e] = wbuf[lr * 16 + lc + e];
            if (EPI == 1) {
#pragma unroll
                for (int e = 0; e < 8; e++) v[e] *= gamma[(n & (H_ - 1)) + e];
            }
            *(float4*)&C[(size_t)m * ldc + n]     = make_float4(v[0], v[1], v[2], v[3]);
            *(float4*)&C[(size_t)m * ldc + n + 4] = make_float4(v[4], v[5], v[6], v[7]);
            __syncwarp();
        }
    }
}

// ---------------------------------------------------------------------------
// Chunk-parallel scan.  idx -> (b, chunk j, h);  h fastest for coalescing.
// ---------------------------------------------------------------------------
__global__ void scanA_kernel(const float* __restrict__ bxby,
                             float* __restrict__ e1, float* __restrict__ e2) {
    int idx = blockIdx.x * blockDim.x + threadIdx.x;    // B*C*H
    int h = idx & (H_ - 1);
    int j = (idx >> 10) & (C_ - 1);
    int b = idx >> 14;
    float gg = d_g[h], pp = d_phi[h];
    float c1 = 0.f, c2 = 0.f;
    const float* base = bxby + ((size_t)(b * T_ + j * L_)) * (2 * H_) + h;
#pragma unroll 4
    for (int t = 0; t < L_; t++) {
        float bx = base[t * (2 * H_)];
        float by = base[t * (2 * H_) + H_];
        float n1 = fmaf(gg, c1, fmaf(-pp, c2, bx));
        float n2 = fmaf(pp, c1, fmaf(gg, c2, by));
        c1 = n1; c2 = n2;
    }
    e1[idx] = c1; e2[idx] = c2;
}

__global__ void combine_kernel(const float* __restrict__ e1,
                               const float* __restrict__ e2,
                               const float* __restrict__ hc1,
                               const float* __restrict__ hc2,
                               float* __restrict__ i1, float* __restrict__ i2) {
    int idx = blockIdx.x * blockDim.x + threadIdx.x;    // B*H
    int h = idx & (H_ - 1);
    int b = idx >> 10;
    float lr = d_g[h], li = d_phi[h];
#pragma unroll
    for (int s = 0; s < 7; s++) {          // lambda^128
        float nr = lr * lr - li * li;
        float ni = 2.0f * lr * li;
        lr = nr; li = ni;
    }
    float c1 = hc1[idx], c2 = hc2[idx];
#pragma unroll
    for (int j = 0; j < C_; j++) {
        int eidx = (b * C_ + j) * H_ + h;
        i1[eidx] = c1; i2[eidx] = c2;
        float n1 = lr * c1 - li * c2 + e1[eidx];
        float n2 = li * c1 + lr * c2 + e2[eidx];
        c1 = n1; c2 = n2;
    }
}

__global__ void scanB_kernel(const float* __restrict__ bxby,
                             const float* __restrict__ i1,
                             const float* __restrict__ i2,
                             float* __restrict__ out) {
    int idx = blockIdx.x * blockDim.x + threadIdx.x;    // B*C*H
    int h = idx & (H_ - 1);
    int j = (idx >> 10) & (C_ - 1);
    int b = idx >> 14;
    float gg = d_g[h], pp = d_phi[h];
    float c1 = i1[idx], c2 = i2[idx];
    const float* base  = bxby + ((size_t)(b * T_ + j * L_)) * (2 * H_) + h;
    float*       ybase = out  + ((size_t)(b * T_ + j * L_)) * (2 * H_) + h;
#pragma unroll 4
    for (int t = 0; t < L_; t++) {
        float bx = base[t * (2 * H_)];
        float by = base[t * (2 * H_) + H_];
        float n1 = fmaf(gg, c1, fmaf(-pp, c2, bx));
        float n2 = fmaf(pp, c1, fmaf(gg, c2, by));
        c1 = n1; c2 = n2;
        ybase[t * (2 * H_)]      = c1;
        ybase[t * (2 * H_) + H_] = c2;
    }
    if (j == C_ - 1) {
        size_t y_elems = (size_t)B_ * T_ * (2 * H_);
        out[y_elems + b * H_ + h]            = c1;
        out[y_elems + B_ * H_ + b * H_ + h]  = c2;
    }
}

// ---------------------------------------------------------------------------
// Launch
// ---------------------------------------------------------------------------
extern "C" void kernel_launch(void* const* d_in, const int* in_sizes, int n_in,
                              void* d_out, int out_size) {
    const float* x         = (const float*)d_in[0];
    const float* nu_log    = (const float*)d_in[1];
    const float* theta_log = (const float*)d_in[2];
    const float* U1        = (const float*)d_in[3];
    const float* U2        = (const float*)d_in[4];
    const float* V1        = (const float*)d_in[5];
    const float* V2        = (const float*)d_in[6];
    const float* hc1       = (const float*)d_in[7];
    const float* hc2       = (const float*)d_in[8];
    float* out = (float*)d_out;

    float *tmp, *bxby, *gamma, *e1, *e2, *i1, *i2;
    cudaGetSymbolAddress((void**)&tmp,   d_tmp);
    cudaGetSymbolAddress((void**)&bxby,  d_bxby);
    cudaGetSymbolAddress((void**)&gamma, d_gamma);
    cudaGetSymbolAddress((void**)&e1, d_e1);
    cudaGetSymbolAddress((void**)&e2, d_e2);
    cudaGetSymbolAddress((void**)&i1, d_i1);
    cudaGetSymbolAddress((void**)&i2, d_i2);

    param_kernel<<<(H_ + 255) / 256, 256>>>(nu_log, theta_log);

    // Stage 1: tmp[:,0:128] = x@U1, tmp[:,128:256] = x@U2   (K=1024)
    tf32_gemm<0, 0><<<dim3(2 * R_ / 64, M_ / 128), 256>>>(
        x, D_, U1, U2, R_, R_, D_, tmp, 2 * R_, nullptr);

    // Stage 2: bxby[:,0:H] = (tmp1@V1)*gamma, bxby[:,H:2H] = (tmp2@V2)*gamma (K=128)
    tf32_gemm<1, 1><<<dim3(2 * H_ / 64, M_ / 128), 256>>>(
        tmp, 2 * R_, V1, V2, H_, H_, R_, bxby, 2 * H_, gamma);

    // Stage 3: chunk-parallel scan
    scanA_kernel<<<(B_ * C_ * H_) / 256, 256>>>(bxby, e1, e2);
    combine_kernel<<<(B_ * H_) / 256, 256>>>(e1, e2, hc1, hc2, i1, i2);
    scanB_kernel<<<(B_ * C_ * H_) / 256, 256>>>(bxby, i1, i2, out);
}